// round 1
// baseline (speedup 1.0000x reference)
#include <cuda_runtime.h>
#include <math.h>

#define M_TOK   100352        // 2048 windows * 49  ==  8 * 112 * 112
#define C_DIM   192
#define NHEADS  6
#define HDIM    32
#define HIDDEN  768

// -------- scratch (device globals; no allocation allowed) --------
__device__ float g_xw  [(size_t)M_TOK * C_DIM];     // LN1 + shifted window partition
__device__ float g_qkv [(size_t)M_TOK * 3 * C_DIM]; // qkv projection
__device__ float g_att [(size_t)M_TOK * C_DIM];     // attention output (window layout)
__device__ float g_x   [(size_t)M_TOK * C_DIM];     // residual stream after proj
__device__ float g_ln2 [(size_t)M_TOK * C_DIM];     // LN2 output
__device__ float g_h   [(size_t)M_TOK * HIDDEN];    // MLP hidden

// ---------------- helpers ----------------
__device__ __forceinline__ float warp_sum(float v) {
#pragma unroll
    for (int o = 16; o > 0; o >>= 1) v += __shfl_xor_sync(0xffffffffu, v, o);
    return v;
}
__device__ __forceinline__ float warp_max(float v) {
#pragma unroll
    for (int o = 16; o > 0; o >>= 1) v = fmaxf(v, __shfl_xor_sync(0xffffffffu, v, o));
    return v;
}

// ---------------- LayerNorm (optionally fused with shift + window gather) ----------------
// GATHER=true : reads query[b, (wi*7+i+3)%112, (wj*7+j+3)%112, :] -> out[token,:]
// GATHER=false: plain row LN
template <bool GATHER>
__global__ void ln_kernel(const float* __restrict__ in,
                          const float* __restrict__ gamma,
                          const float* __restrict__ beta,
                          float* __restrict__ out) {
    int t = blockIdx.x;          // token 0..100351
    int c = threadIdx.x;         // 0..191
    int src;
    if (GATHER) {
        int w  = t / 49, n = t % 49;
        int bb = w >> 8;            // image
        int r  = w & 255;
        int wi = r >> 4, wj = r & 15;
        int i  = n / 7,  j  = n % 7;
        int hh = wi * 7 + i + 3; if (hh >= 112) hh -= 112;
        int ww = wj * 7 + j + 3; if (ww >= 112) ww -= 112;
        src = bb * 12544 + hh * 112 + ww;
    } else {
        src = t;
    }
    float v = in[(size_t)src * C_DIM + c];

    __shared__ float s1[6], s2[6];
    int wid = c >> 5, lid = c & 31;
    float s = warp_sum(v);
    if (lid == 0) s1[wid] = s;
    __syncthreads();
    float mean = (s1[0] + s1[1] + s1[2] + s1[3] + s1[4] + s1[5]) * (1.0f / 192.0f);
    float d = v - mean;
    float sq = warp_sum(d * d);
    if (lid == 0) s2[wid] = sq;
    __syncthreads();
    float var = (s2[0] + s2[1] + s2[2] + s2[3] + s2[4] + s2[5]) * (1.0f / 192.0f);
    out[(size_t)t * C_DIM + c] = d * rsqrtf(var + 1e-5f) * gamma[c] + beta[c];
}

// ---------------- Tiled fp32 GEMM: C[M,N] = A[M,K] @ W[K,N] (+epilogue) ----------------
// BM=BN=64, BK=16, 256 threads, 4x4 micro-tile per thread.
enum { EPI_BIAS = 0, EPI_GELU = 1, EPI_SCATTER = 2, EPI_RES = 3 };

template <int EPI>
__global__ void gemm_kernel(const float* __restrict__ A,
                            const float* __restrict__ Wm,
                            const float* __restrict__ bias,
                            float* __restrict__ Cout,
                            int M, int N, int K,
                            const float* __restrict__ res) {
    const int BM = 64, BN = 64, BK = 16;
    __shared__ float As[BM][BK];
    __shared__ float Bs[BK][BN + 4];

    int tid = threadIdx.x;           // 0..255
    int tx = tid & 15, ty = tid >> 4;
    int mBase = blockIdx.y * BM;
    int nBase = blockIdx.x * BN;

    float acc[4][4];
#pragma unroll
    for (int r = 0; r < 4; r++)
#pragma unroll
        for (int c = 0; c < 4; c++) acc[r][c] = 0.0f;

    int aIdx = tid * 4;
    int ar = aIdx >> 4, ac = aIdx & 15;
    int br = aIdx >> 6, bc = aIdx & 63;

    for (int k0 = 0; k0 < K; k0 += BK) {
        float4 av = *(const float4*)(A + (size_t)(mBase + ar) * K + k0 + ac);
        *(float4*)&As[ar][ac] = av;
        float4 bv = *(const float4*)(Wm + (size_t)(k0 + br) * N + nBase + bc);
        Bs[br][bc + 0] = bv.x; Bs[br][bc + 1] = bv.y;
        Bs[br][bc + 2] = bv.z; Bs[br][bc + 3] = bv.w;
        __syncthreads();
#pragma unroll
        for (int kk = 0; kk < BK; kk++) {
            float a[4], b[4];
#pragma unroll
            for (int r = 0; r < 4; r++) a[r] = As[ty * 4 + r][kk];
#pragma unroll
            for (int c = 0; c < 4; c++) b[c] = Bs[kk][tx * 4 + c];
#pragma unroll
            for (int r = 0; r < 4; r++)
#pragma unroll
                for (int c = 0; c < 4; c++) acc[r][c] = fmaf(a[r], b[c], acc[r][c]);
        }
        __syncthreads();
    }

#pragma unroll
    for (int r = 0; r < 4; r++) {
        int row = mBase + ty * 4 + r;
        int dst = row;
        if (EPI == EPI_SCATTER) {
            // window reverse + reverse shift: token -> (b, h, w)
            int w  = row / 49, n = row % 49;
            int bb = w >> 8;
            int rr = w & 255;
            int wi = rr >> 4, wj = rr & 15;
            int i  = n / 7,  j  = n % 7;
            int hh = wi * 7 + i + 3; if (hh >= 112) hh -= 112;
            int ww = wj * 7 + j + 3; if (ww >= 112) ww -= 112;
            dst = bb * 12544 + hh * 112 + ww;
        }
#pragma unroll
        for (int c = 0; c < 4; c++) {
            int col = nBase + tx * 4 + c;
            float v = acc[r][c] + bias[col];
            if (EPI == EPI_GELU) {
                v = 0.5f * v * (1.0f + erff(v * 0.70710678118654752f));
                Cout[(size_t)row * N + col] = v;
            } else if (EPI == EPI_SCATTER) {
                Cout[(size_t)dst * N + col] = v + res[(size_t)dst * N + col];
            } else if (EPI == EPI_RES) {
                Cout[(size_t)row * N + col] = v + res[(size_t)row * N + col];
            } else {
                Cout[(size_t)row * N + col] = v;
            }
        }
    }
}

// ---------------- Windowed attention: one block per (window, head) ----------------
__global__ void attn_kernel(const float* __restrict__ qkv,
                            const float* __restrict__ rpb,   // [169, 6]
                            float* __restrict__ out) {
    int blk = blockIdx.x;
    int w = blk / NHEADS;
    int h = blk - w * NHEADS;

    __shared__ float sq[49][32], sk[49][32], sv[49][32];
    __shared__ float sa[49][49];

    int tid = threadIdx.x;        // 256 threads
    const float scale = 0.17677669529663687f;   // 32^-0.5

    for (int idx = tid; idx < 49 * 32; idx += 256) {
        int n = idx >> 5, d = idx & 31;
        size_t base = ((size_t)(w * 49 + n)) * (3 * C_DIM) + h * HDIM + d;
        sq[n][d] = qkv[base] * scale;
        sk[n][d] = qkv[base + C_DIM];
        sv[n][d] = qkv[base + 2 * C_DIM];
    }
    __syncthreads();

    int r  = w & 255;
    int wi = r >> 4, wj = r & 15;

    for (int e = tid; e < 49 * 49; e += 256) {
        int n = e / 49, m = e - n * 49;
        float dot = 0.0f;
#pragma unroll
        for (int d = 0; d < 32; d++) dot = fmaf(sq[n][d], sk[m][d], dot);
        int i1 = n / 7, j1 = n % 7, i2 = m / 7, j2 = m % 7;
        float b = rpb[((i1 - i2 + 6) * 13 + (j1 - j2 + 6)) * NHEADS + h];
        // shift-mask computed analytically (matches _attn_mask for Hp=Wp=112, ws=7, ss=3)
        int hp1 = wi * 7 + i1, wp1 = wj * 7 + j1;
        int hp2 = wi * 7 + i2, wp2 = wj * 7 + j2;
        int reg1 = (hp1 < 105 ? 0 : (hp1 < 109 ? 1 : 2)) * 3 + (wp1 < 105 ? 0 : (wp1 < 109 ? 1 : 2));
        int reg2 = (hp2 < 105 ? 0 : (hp2 < 109 ? 1 : 2)) * 3 + (wp2 < 105 ? 0 : (wp2 < 109 ? 1 : 2));
        sa[n][m] = dot + b + (reg1 == reg2 ? 0.0f : -100.0f);
    }
    __syncthreads();

    // softmax over rows (49 elems); one warp per row, 8 warps round-robin
    int wid = tid >> 5, lid = tid & 31;
    for (int n = wid; n < 49; n += 8) {
        float v1 = sa[n][lid];
        float v2 = (lid < 17) ? sa[n][lid + 32] : -1e30f;
        float mx = warp_max(fmaxf(v1, v2));
        float e1 = __expf(v1 - mx);
        float e2 = (lid < 17) ? __expf(v2 - mx) : 0.0f;
        float s = warp_sum(e1 + e2);
        float inv = 1.0f / s;
        sa[n][lid] = e1 * inv;
        if (lid < 17) sa[n][lid + 32] = e2 * inv;
    }
    __syncthreads();

    for (int idx = tid; idx < 49 * 32; idx += 256) {
        int n = idx >> 5, d = idx & 31;
        float o = 0.0f;
#pragma unroll
        for (int m = 0; m < 49; m++) o = fmaf(sa[n][m], sv[m][d], o);
        out[((size_t)(w * 49 + n)) * C_DIM + h * HDIM + d] = o;
    }
}

// ---------------- launch ----------------
extern "C" void kernel_launch(void* const* d_in, const int* in_sizes, int n_in,
                              void* d_out, int out_size) {
    const float* query   = (const float*)d_in[0];
    const float* norm1_g = (const float*)d_in[1];
    const float* norm1_b = (const float*)d_in[2];
    const float* qkv_w   = (const float*)d_in[3];
    const float* qkv_b   = (const float*)d_in[4];
    const float* rpb     = (const float*)d_in[5];
    const float* proj_w  = (const float*)d_in[6];
    const float* proj_b  = (const float*)d_in[7];
    const float* norm2_g = (const float*)d_in[8];
    const float* norm2_b = (const float*)d_in[9];
    const float* fc1_w   = (const float*)d_in[10];
    const float* fc1_b   = (const float*)d_in[11];
    const float* fc2_w   = (const float*)d_in[12];
    const float* fc2_b   = (const float*)d_in[13];
    float* out = (float*)d_out;

    float *xw, *qkvp, *att, *x, *ln2, *hbuf;
    cudaGetSymbolAddress((void**)&xw,   g_xw);
    cudaGetSymbolAddress((void**)&qkvp, g_qkv);
    cudaGetSymbolAddress((void**)&att,  g_att);
    cudaGetSymbolAddress((void**)&x,    g_x);
    cudaGetSymbolAddress((void**)&ln2,  g_ln2);
    cudaGetSymbolAddress((void**)&hbuf, g_h);

    // 1) LN1 + shift + window partition
    ln_kernel<true><<<M_TOK, 192>>>(query, norm1_g, norm1_b, xw);

    // 2) qkv = xw @ qkv_w + b      [100352,192]x[192,576]
    gemm_kernel<EPI_BIAS><<<dim3(576 / 64, M_TOK / 64), 256>>>(
        xw, qkv_w, qkv_b, qkvp, M_TOK, 576, 192, nullptr);

    // 3) windowed attention
    attn_kernel<<<2048 * NHEADS, 256>>>(qkvp, rpb, att);

    // 4) proj + window reverse + unshift + residual(query)   [100352,192]x[192,192]
    gemm_kernel<EPI_SCATTER><<<dim3(192 / 64, M_TOK / 64), 256>>>(
        att, proj_w, proj_b, x, M_TOK, 192, 192, query);

    // 5) LN2
    ln_kernel<false><<<M_TOK, 192>>>(x, norm2_g, norm2_b, ln2);

    // 6) fc1 + exact GELU          [100352,192]x[192,768]
    gemm_kernel<EPI_GELU><<<dim3(768 / 64, M_TOK / 64), 256>>>(
        ln2, fc1_w, fc1_b, hbuf, M_TOK, HIDDEN, 192, nullptr);

    // 7) fc2 + residual(x) -> out  [100352,768]x[768,192]
    gemm_kernel<EPI_RES><<<dim3(192 / 64, M_TOK / 64), 256>>>(
        hbuf, fc2_w, fc2_b, out, M_TOK, 192, HIDDEN, x);
}

// round 3
// speedup vs baseline: 2.2202x; 2.2202x over previous
#include <cuda_runtime.h>
#include <cuda_bf16.h>
#include <math.h>
#include <stdint.h>

#define M_TOK   100352        // 2048 windows * 49  ==  8 * 112 * 112
#define C_DIM   192
#define NHEADS  6
#define HDIM    32
#define HIDDEN  768

// GEMM tiling
#define BM 128
#define BN 64
#define BK 32
#define PITCH 40              // smem row pitch in bf16 (80 B) -> conflict-free frags
#define STAGE_BYTES (BM*PITCH*2*2 + BN*PITCH*2*2)   // Ah+Al + Bh+Bl = 30720
#define OFF_AH 0
#define OFF_AL (BM*PITCH*2)
#define OFF_BH (2*BM*PITCH*2)
#define OFF_BL (2*BM*PITCH*2 + BN*PITCH*2)

// ---------------- scratch (device globals) ----------------
__device__ __nv_bfloat16 g_xw_h [(size_t)M_TOK * C_DIM];
__device__ __nv_bfloat16 g_xw_l [(size_t)M_TOK * C_DIM];
__device__ float         g_qkv  [(size_t)M_TOK * 3 * C_DIM];
__device__ __nv_bfloat16 g_att_h[(size_t)M_TOK * C_DIM];
__device__ __nv_bfloat16 g_att_l[(size_t)M_TOK * C_DIM];
__device__ float         g_x    [(size_t)M_TOK * C_DIM];
__device__ __nv_bfloat16 g_ln2_h[(size_t)M_TOK * C_DIM];
__device__ __nv_bfloat16 g_ln2_l[(size_t)M_TOK * C_DIM];
__device__ __nv_bfloat16 g_h_h  [(size_t)M_TOK * HIDDEN];
__device__ __nv_bfloat16 g_h_l  [(size_t)M_TOK * HIDDEN];
// transposed bf16 weights [N, K] hi/lo
__device__ __nv_bfloat16 g_wqkv_h[576 * 192], g_wqkv_l[576 * 192];
__device__ __nv_bfloat16 g_wprj_h[192 * 192], g_wprj_l[192 * 192];
__device__ __nv_bfloat16 g_wfc1_h[768 * 192], g_wfc1_l[768 * 192];
__device__ __nv_bfloat16 g_wfc2_h[192 * 768], g_wfc2_l[192 * 768];

// ---------------- helpers ----------------
__device__ __forceinline__ uint32_t smem_u32(const void* p) {
    uint32_t a;
    asm("{ .reg .u64 t; cvta.to.shared.u64 t, %1; cvt.u32.u64 %0, t; }" : "=r"(a) : "l"(p));
    return a;
}
__device__ __forceinline__ void cp16(uint32_t sa, const void* g) {
    asm volatile("cp.async.cg.shared.global [%0], [%1], 16;" :: "r"(sa), "l"(g));
}
__device__ __forceinline__ void cp_commit() { asm volatile("cp.async.commit_group;"); }
template <int N>
__device__ __forceinline__ void cp_wait() { asm volatile("cp.async.wait_group %0;" :: "n"(N)); }

__device__ __forceinline__ void mma16816(float* c, const uint32_t* a, const uint32_t* b) {
    asm volatile("mma.sync.aligned.m16n8k16.row.col.f32.bf16.bf16.f32 "
        "{%0,%1,%2,%3}, {%4,%5,%6,%7}, {%8,%9}, {%0,%1,%2,%3};"
        : "+f"(c[0]), "+f"(c[1]), "+f"(c[2]), "+f"(c[3])
        : "r"(a[0]), "r"(a[1]), "r"(a[2]), "r"(a[3]), "r"(b[0]), "r"(b[1]));
}
__device__ __forceinline__ void split2(float v, __nv_bfloat16& h, __nv_bfloat16& l) {
    h = __float2bfloat16(v);
    l = __float2bfloat16(v - __bfloat162float(h));
}
__device__ __forceinline__ float gelu_exact(float v) {
    return 0.5f * v * (1.0f + erff(v * 0.70710678118654752f));
}
__device__ __forceinline__ float warp_sum(float v) {
#pragma unroll
    for (int o = 16; o > 0; o >>= 1) v += __shfl_xor_sync(0xffffffffu, v, o);
    return v;
}
__device__ __forceinline__ float warp_max(float v) {
#pragma unroll
    for (int o = 16; o > 0; o >>= 1) v = fmaxf(v, __shfl_xor_sync(0xffffffffu, v, o));
    return v;
}
__device__ __forceinline__ int scatter_dst(int row) {
    int w = row / 49, n = row % 49;
    int bb = w >> 8, rr = w & 255;
    int wi = rr >> 4, wj = rr & 15;
    int i = n / 7, j = n % 7;
    int hh = wi * 7 + i + 3; if (hh >= 112) hh -= 112;
    int ww = wj * 7 + j + 3; if (ww >= 112) ww -= 112;
    return bb * 12544 + hh * 112 + ww;
}

// ---------------- weight transpose + split: W[K,N] -> Wt_hi/lo [N,K] ----------------
__global__ void wprep_kernel(const float* __restrict__ W, __nv_bfloat16* __restrict__ Th,
                             __nv_bfloat16* __restrict__ Tl, int K, int N) {
    int i = blockIdx.x * 256 + threadIdx.x;
    if (i >= K * N) return;
    int k = i / N, n = i - k * N;
    __nv_bfloat16 h, l;
    split2(W[i], h, l);
    Th[(size_t)n * K + k] = h;
    Tl[(size_t)n * K + k] = l;
}

// ---------------- LayerNorm (+ optional shift/window gather), split bf16 out ----------------
template <bool GATHER>
__global__ void ln_kernel(const float* __restrict__ in,
                          const float* __restrict__ gamma, const float* __restrict__ beta,
                          __nv_bfloat16* __restrict__ oh, __nv_bfloat16* __restrict__ ol) {
    int t = blockIdx.x, c = threadIdx.x;
    int src = GATHER ? scatter_dst(t) : t;   // gather uses same cyclic map (shift by +3 both ways mod 7 grid)
    if (GATHER) {
        // forward shift: x[b, h, w] sampled at (h+3, w+3) mod 112 — same formula as scatter_dst
        // scatter_dst(t) already computes b*12544 + ((wi*7+i+3)%112)*112 + ((wj*7+j+3)%112)
    }
    float v = in[(size_t)src * C_DIM + c];
    __shared__ float s1[6], s2[6];
    int wid = c >> 5, lid = c & 31;
    float s = warp_sum(v);
    if (lid == 0) s1[wid] = s;
    __syncthreads();
    float mean = (s1[0] + s1[1] + s1[2] + s1[3] + s1[4] + s1[5]) * (1.0f / 192.0f);
    float d = v - mean;
    float sq = warp_sum(d * d);
    if (lid == 0) s2[wid] = sq;
    __syncthreads();
    float var = (s2[0] + s2[1] + s2[2] + s2[3] + s2[4] + s2[5]) * (1.0f / 192.0f);
    float o = d * rsqrtf(var + 1e-5f) * gamma[c] + beta[c];
    __nv_bfloat16 h, l;
    split2(o, h, l);
    oh[(size_t)t * C_DIM + c] = h;
    ol[(size_t)t * C_DIM + c] = l;
}

// ---------------- HMMA split-bf16 GEMM ----------------
// C[M, Nout] = A[M, K] @ Wt[Nout, K]^T ; A hi/lo bf16, Wt hi/lo bf16 (K-major)
// 3 products: Ah*Bh + Ah*Bl + Al*Bh into fp32 acc.
enum { EPI_F32 = 0, EPI_GELU = 1, EPI_SCATTER = 2, EPI_RES = 3 };

template <int EPI>
__global__ __launch_bounds__(256)
void gemm_mma(const __nv_bfloat16* __restrict__ Ah, const __nv_bfloat16* __restrict__ Al,
              const __nv_bfloat16* __restrict__ Bh, const __nv_bfloat16* __restrict__ Bl,
              const float* __restrict__ bias, const float* __restrict__ res,
              float* __restrict__ outf, __nv_bfloat16* __restrict__ outh,
              __nv_bfloat16* __restrict__ outl, int K, int Nout) {
    extern __shared__ __align__(16) char smem[];
    int tid = threadIdx.x;
    int wid = tid >> 5, lid = tid & 31;
    int wm = wid & 3, wn = wid >> 2;           // warp grid 4 x 2
    int g = lid >> 2, tq = lid & 3;
    int mBase = blockIdx.y * BM;
    int nBase = blockIdx.x * BN;
    uint32_t sb = smem_u32(smem);

    float acc[2][4][4];
#pragma unroll
    for (int a = 0; a < 2; a++)
#pragma unroll
        for (int b = 0; b < 4; b++)
#pragma unroll
            for (int c = 0; c < 4; c++) acc[a][b][c] = 0.0f;

    int nch = K / BK;

    // ---- async load of one stage ----
    auto issue = [&](int c) {
        int p = c & 1;
        uint32_t sbase = sb + p * STAGE_BYTES;
        int k0 = c * BK;
        // 1536 16B chunks: [0,512) Ah, [512,1024) Al, [1024,1280) Bh, [1280,1536) Bl
#pragma unroll
        for (int u = 0; u < 6; u++) {
            int ch = tid + u * 256;
            if (ch < 512) {
                int r = ch >> 2, cc = ch & 3;
                cp16(sbase + OFF_AH + r * (PITCH * 2) + cc * 16,
                     Ah + (size_t)(mBase + r) * K + k0 + cc * 8);
            } else if (ch < 1024) {
                int q = ch - 512;
                int r = q >> 2, cc = q & 3;
                cp16(sbase + OFF_AL + r * (PITCH * 2) + cc * 16,
                     Al + (size_t)(mBase + r) * K + k0 + cc * 8);
            } else if (ch < 1280) {
                int q = ch - 1024;
                int r = q >> 2, cc = q & 3;
                cp16(sbase + OFF_BH + r * (PITCH * 2) + cc * 16,
                     Bh + (size_t)(nBase + r) * K + k0 + cc * 8);
            } else {
                int q = ch - 1280;
                int r = q >> 2, cc = q & 3;
                cp16(sbase + OFF_BL + r * (PITCH * 2) + cc * 16,
                     Bl + (size_t)(nBase + r) * K + k0 + cc * 8);
            }
        }
        cp_commit();
    };

    issue(0);
    for (int c = 0; c < nch; c++) {
        if (c + 1 < nch) { issue(c + 1); cp_wait<1>(); }
        else             { cp_wait<0>(); }
        __syncthreads();

        const char* buf = smem + (c & 1) * STAGE_BYTES;
#pragma unroll
        for (int kk = 0; kk < BK; kk += 16) {
            uint32_t ahf[2][4], alf[2][4], bhf[4][2], blf[4][2];
#pragma unroll
            for (int mt = 0; mt < 2; mt++) {
                int r0 = wm * 32 + mt * 16 + g;
                int kb = (kk + tq * 2) * 2;
#pragma unroll
                for (int hv = 0; hv < 2; hv++) {
                    const char* base = buf + (hv ? OFF_AL : OFF_AH);
                    uint32_t v0 = *(const uint32_t*)(base + r0 * (PITCH * 2) + kb);
                    uint32_t v1 = *(const uint32_t*)(base + (r0 + 8) * (PITCH * 2) + kb);
                    uint32_t v2 = *(const uint32_t*)(base + r0 * (PITCH * 2) + kb + 16);
                    uint32_t v3 = *(const uint32_t*)(base + (r0 + 8) * (PITCH * 2) + kb + 16);
                    uint32_t* dst = hv ? alf[mt] : ahf[mt];
                    dst[0] = v0; dst[1] = v1; dst[2] = v2; dst[3] = v3;
                }
            }
#pragma unroll
            for (int nt = 0; nt < 4; nt++) {
                int n0 = wn * 32 + nt * 8 + g;
                int kb = (kk + tq * 2) * 2;
                bhf[nt][0] = *(const uint32_t*)(buf + OFF_BH + n0 * (PITCH * 2) + kb);
                bhf[nt][1] = *(const uint32_t*)(buf + OFF_BH + n0 * (PITCH * 2) + kb + 16);
                blf[nt][0] = *(const uint32_t*)(buf + OFF_BL + n0 * (PITCH * 2) + kb);
                blf[nt][1] = *(const uint32_t*)(buf + OFF_BL + n0 * (PITCH * 2) + kb + 16);
            }
#pragma unroll
            for (int mt = 0; mt < 2; mt++)
#pragma unroll
                for (int nt = 0; nt < 4; nt++) {
                    mma16816(acc[mt][nt], ahf[mt], bhf[nt]);
                    mma16816(acc[mt][nt], ahf[mt], blf[nt]);
                    mma16816(acc[mt][nt], alf[mt], bhf[nt]);
                }
        }
        __syncthreads();
    }

    // ---- epilogue ----
#pragma unroll
    for (int mt = 0; mt < 2; mt++) {
#pragma unroll
        for (int half = 0; half < 2; half++) {   // c0/c1 (row) vs c2/c3 (row+8)
            int row = mBase + wm * 32 + mt * 16 + g + half * 8;
            int dst = (EPI == EPI_SCATTER) ? scatter_dst(row) : row;
#pragma unroll
            for (int nt = 0; nt < 4; nt++) {
                int col = nBase + wn * 32 + nt * 8 + tq * 2;
                float v0 = acc[mt][nt][half * 2 + 0] + bias[col];
                float v1 = acc[mt][nt][half * 2 + 1] + bias[col + 1];
                if (EPI == EPI_GELU) {
                    v0 = gelu_exact(v0); v1 = gelu_exact(v1);
                    __nv_bfloat16 h0, l0, h1, l1;
                    split2(v0, h0, l0); split2(v1, h1, l1);
                    __nv_bfloat162 hp; hp.x = h0; hp.y = h1;
                    __nv_bfloat162 lp; lp.x = l0; lp.y = l1;
                    *(__nv_bfloat162*)(outh + (size_t)row * Nout + col) = hp;
                    *(__nv_bfloat162*)(outl + (size_t)row * Nout + col) = lp;
                } else if (EPI == EPI_SCATTER || EPI == EPI_RES) {
                    size_t o = (size_t)dst * Nout + col;
                    float2 rv = *(const float2*)(res + o);
                    float2 w; w.x = v0 + rv.x; w.y = v1 + rv.y;
                    *(float2*)(outf + o) = w;
                } else {
                    float2 w; w.x = v0; w.y = v1;
                    *(float2*)(outf + (size_t)row * Nout + col) = w;
                }
            }
        }
    }
}

// ---------------- Windowed attention: one block per (window, head) ----------------
__global__ void attn_kernel(const float* __restrict__ qkv,
                            const float* __restrict__ rpb,
                            __nv_bfloat16* __restrict__ oh, __nv_bfloat16* __restrict__ ol) {
    int blk = blockIdx.x;
    int w = blk / NHEADS;
    int h = blk - w * NHEADS;

    __shared__ float sq[49][32], sk[49][33], sv[49][32];
    __shared__ float sa[49][49];

    int tid = threadIdx.x;
    const float scale = 0.17677669529663687f;

    for (int idx = tid; idx < 49 * 32; idx += 256) {
        int n = idx >> 5, d = idx & 31;
        size_t base = ((size_t)(w * 49 + n)) * (3 * C_DIM) + h * HDIM + d;
        sq[n][d] = qkv[base] * scale;
        sk[n][d] = qkv[base + C_DIM];
        sv[n][d] = qkv[base + 2 * C_DIM];
    }
    __syncthreads();

    int r = w & 255;
    int wi = r >> 4, wj = r & 15;

    for (int e = tid; e < 49 * 49; e += 256) {
        int n = e / 49, m = e - n * 49;
        float dot = 0.0f;
#pragma unroll
        for (int d = 0; d < 32; d++) dot = fmaf(sq[n][d], sk[m][d], dot);
        int i1 = n / 7, j1 = n % 7, i2 = m / 7, j2 = m % 7;
        float b = rpb[((i1 - i2 + 6) * 13 + (j1 - j2 + 6)) * NHEADS + h];
        int hp1 = wi * 7 + i1, wp1 = wj * 7 + j1;
        int hp2 = wi * 7 + i2, wp2 = wj * 7 + j2;
        int reg1 = (hp1 < 105 ? 0 : (hp1 < 109 ? 1 : 2)) * 3 + (wp1 < 105 ? 0 : (wp1 < 109 ? 1 : 2));
        int reg2 = (hp2 < 105 ? 0 : (hp2 < 109 ? 1 : 2)) * 3 + (wp2 < 105 ? 0 : (wp2 < 109 ? 1 : 2));
        sa[n][m] = dot + b + (reg1 == reg2 ? 0.0f : -100.0f);
    }
    __syncthreads();

    int wid = tid >> 5, lid = tid & 31;
    for (int n = wid; n < 49; n += 8) {
        float v1 = sa[n][lid];
        float v2 = (lid < 17) ? sa[n][lid + 32] : -1e30f;
        float mx = warp_max(fmaxf(v1, v2));
        float e1 = __expf(v1 - mx);
        float e2 = (lid < 17) ? __expf(v2 - mx) : 0.0f;
        float s = warp_sum(e1 + e2);
        float inv = 1.0f / s;
        sa[n][lid] = e1 * inv;
        if (lid < 17) sa[n][lid + 32] = e2 * inv;
    }
    __syncthreads();

    for (int idx = tid; idx < 49 * 32; idx += 256) {
        int n = idx >> 5, d = idx & 31;
        float o = 0.0f;
#pragma unroll
        for (int m = 0; m < 49; m++) o = fmaf(sa[n][m], sv[m][d], o);
        size_t oidx = ((size_t)(w * 49 + n)) * C_DIM + h * HDIM + d;
        __nv_bfloat16 hh, ll;
        split2(o, hh, ll);
        oh[oidx] = hh;
        ol[oidx] = ll;
    }
}

// ---------------- launch ----------------
extern "C" void kernel_launch(void* const* d_in, const int* in_sizes, int n_in,
                              void* d_out, int out_size) {
    const float* query   = (const float*)d_in[0];
    const float* norm1_g = (const float*)d_in[1];
    const float* norm1_b = (const float*)d_in[2];
    const float* qkv_w   = (const float*)d_in[3];
    const float* qkv_b   = (const float*)d_in[4];
    const float* rpb     = (const float*)d_in[5];
    const float* proj_w  = (const float*)d_in[6];
    const float* proj_b  = (const float*)d_in[7];
    const float* norm2_g = (const float*)d_in[8];
    const float* norm2_b = (const float*)d_in[9];
    const float* fc1_w   = (const float*)d_in[10];
    const float* fc1_b   = (const float*)d_in[11];
    const float* fc2_w   = (const float*)d_in[12];
    const float* fc2_b   = (const float*)d_in[13];
    float* out = (float*)d_out;

    __nv_bfloat16 *xwh, *xwl, *atth, *attl, *ln2h, *ln2l, *hh, *hl;
    __nv_bfloat16 *wqh, *wql, *wph, *wpl, *w1h, *w1l, *w2h, *w2l;
    float *qkvp, *x;
    cudaGetSymbolAddress((void**)&xwh, g_xw_h);   cudaGetSymbolAddress((void**)&xwl, g_xw_l);
    cudaGetSymbolAddress((void**)&qkvp, g_qkv);
    cudaGetSymbolAddress((void**)&atth, g_att_h); cudaGetSymbolAddress((void**)&attl, g_att_l);
    cudaGetSymbolAddress((void**)&x, g_x);
    cudaGetSymbolAddress((void**)&ln2h, g_ln2_h); cudaGetSymbolAddress((void**)&ln2l, g_ln2_l);
    cudaGetSymbolAddress((void**)&hh, g_h_h);     cudaGetSymbolAddress((void**)&hl, g_h_l);
    cudaGetSymbolAddress((void**)&wqh, g_wqkv_h); cudaGetSymbolAddress((void**)&wql, g_wqkv_l);
    cudaGetSymbolAddress((void**)&wph, g_wprj_h); cudaGetSymbolAddress((void**)&wpl, g_wprj_l);
    cudaGetSymbolAddress((void**)&w1h, g_wfc1_h); cudaGetSymbolAddress((void**)&w1l, g_wfc1_l);
    cudaGetSymbolAddress((void**)&w2h, g_wfc2_h); cudaGetSymbolAddress((void**)&w2l, g_wfc2_l);

    const int SMEM = 2 * STAGE_BYTES;   // 61440
    cudaFuncSetAttribute(gemm_mma<EPI_F32>,     cudaFuncAttributeMaxDynamicSharedMemorySize, SMEM);
    cudaFuncSetAttribute(gemm_mma<EPI_GELU>,    cudaFuncAttributeMaxDynamicSharedMemorySize, SMEM);
    cudaFuncSetAttribute(gemm_mma<EPI_SCATTER>, cudaFuncAttributeMaxDynamicSharedMemorySize, SMEM);
    cudaFuncSetAttribute(gemm_mma<EPI_RES>,     cudaFuncAttributeMaxDynamicSharedMemorySize, SMEM);

    // weight prep (transpose + hi/lo split)
    wprep_kernel<<<(192 * 576 + 255) / 256, 256>>>(qkv_w,  wqh, wql, 192, 576);
    wprep_kernel<<<(192 * 192 + 255) / 256, 256>>>(proj_w, wph, wpl, 192, 192);
    wprep_kernel<<<(192 * 768 + 255) / 256, 256>>>(fc1_w,  w1h, w1l, 192, 768);
    wprep_kernel<<<(768 * 192 + 255) / 256, 256>>>(fc2_w,  w2h, w2l, 768, 192);

    // 1) LN1 + shift + window partition (split bf16)
    ln_kernel<true><<<M_TOK, 192>>>(query, norm1_g, norm1_b, xwh, xwl);

    // 2) qkv  [100352,192] x [192,576] -> fp32
    gemm_mma<EPI_F32><<<dim3(576 / BN, M_TOK / BM), 256, SMEM>>>(
        xwh, xwl, wqh, wql, qkv_b, nullptr, qkvp, nullptr, nullptr, 192, 576);

    // 3) windowed attention -> split bf16
    attn_kernel<<<2048 * NHEADS, 256>>>(qkvp, rpb, atth, attl);

    // 4) proj + window reverse + unshift + residual(query)
    gemm_mma<EPI_SCATTER><<<dim3(192 / BN, M_TOK / BM), 256, SMEM>>>(
        atth, attl, wph, wpl, proj_b, query, x, nullptr, nullptr, 192, 192);

    // 5) LN2 (split bf16)
    ln_kernel<false><<<M_TOK, 192>>>(x, norm2_g, norm2_b, ln2h, ln2l);

    // 6) fc1 + GELU -> split bf16
    gemm_mma<EPI_GELU><<<dim3(768 / BN, M_TOK / BM), 256, SMEM>>>(
        ln2h, ln2l, w1h, w1l, fc1_b, nullptr, nullptr, hh, hl, 192, 768);

    // 7) fc2 + residual(x) -> out
    gemm_mma<EPI_RES><<<dim3(192 / BN, M_TOK / BM), 256, SMEM>>>(
        hh, hl, w2h, w2l, fc2_b, x, out, nullptr, nullptr, 768, 192);
}